// round 2
// baseline (speedup 1.0000x reference)
#include <cuda_runtime.h>
#include <cuda_bf16.h>
#include <cstdint>

#define T_DIM 512
#define B_DIM 128
#define E_DIM 256
#define U_DIM 256

// Scratch for xW[t][b][u]  (64 MB fp32 — fits in 126 MB L2)
__device__ float g_xw[T_DIM * B_DIM * U_DIM];

// ---------------- helpers ----------------
__device__ __forceinline__ uint32_t smem_u32(const void* p) {
    uint32_t a;
    asm("{ .reg .u64 t; cvta.to.shared.u64 t, %1; cvt.u32.u64 %0, t; }" : "=r"(a) : "l"(p));
    return a;
}
__device__ __forceinline__ uint32_t packbf(float a, float b) {
    __nv_bfloat162 t = __floats2bfloat162_rn(a, b);
    return *reinterpret_cast<uint32_t*>(&t);
}
__device__ __forceinline__ float blo(uint32_t v) { return __uint_as_float(v << 16); }
__device__ __forceinline__ float bhi(uint32_t v) { return __uint_as_float(v & 0xffff0000u); }

__device__ __forceinline__ void ldsm_x4(uint32_t* r, uint32_t addr) {
    asm volatile("ldmatrix.sync.aligned.m8n8.x4.shared.b16 {%0,%1,%2,%3}, [%4];"
                 : "=r"(r[0]), "=r"(r[1]), "=r"(r[2]), "=r"(r[3]) : "r"(addr));
}
__device__ __forceinline__ void ldsm_x2(uint32_t* r, uint32_t addr) {
    asm volatile("ldmatrix.sync.aligned.m8n8.x2.shared.b16 {%0,%1}, [%2];"
                 : "=r"(r[0]), "=r"(r[1]) : "r"(addr));
}
__device__ __forceinline__ void mma_bf16(float* c, const uint32_t* a, const uint32_t* b) {
    asm volatile("mma.sync.aligned.m16n8k16.row.col.f32.bf16.bf16.f32 "
                 "{%0,%1,%2,%3}, {%4,%5,%6,%7}, {%8,%9}, {%0,%1,%2,%3};"
                 : "+f"(c[0]), "+f"(c[1]), "+f"(c[2]), "+f"(c[3])
                 : "r"(a[0]), "r"(a[1]), "r"(a[2]), "r"(a[3]), "r"(b[0]), "r"(b[1]));
}

// ---------------- Kernel 1: xW[t][b][u] = emb[token(b,t)] . W[u] ----------------
// One CTA per timestep t (512 CTAs, 256 threads / 8 warps).
// A: [128 x 256] bf16 (emb rows), B: [256 x 256] bf16 (W rows, u-major k-contig).
// Padded rows (264 bf16 = 528 B) make ldmatrix conflict-free.

static constexpr int APAD = 264;                     // bf16 elems per smem row
static constexpr int AS_OFF = 0;
static constexpr int BS_OFF = 128 * APAD * 2;        // 67584
static constexpr int XW_SMEM = BS_OFF + 256 * APAD * 2;  // 202752

__global__ void __launch_bounds__(256, 1)
xw_kernel(const int* __restrict__ sentence, const float* __restrict__ emb,
          const float* __restrict__ W) {
    extern __shared__ char smem[];
    const int tid = threadIdx.x, t = blockIdx.x;
    const int wid = tid >> 5, lane = tid & 31;
    const uint32_t sb = smem_u32(smem);

    // --- stage A: 8 threads per row, 4 passes of 32 rows ---
    {
        const int sub = tid & 7;
        #pragma unroll
        for (int p = 0; p < 4; p++) {
            const int r = p * 32 + (tid >> 3);
            const int tok = sentence[r * T_DIM + t];
            const float4* src = reinterpret_cast<const float4*>(emb + (size_t)tok * E_DIM) + sub;
            char* dstrow = smem + AS_OFF + r * (APAD * 2);
            #pragma unroll
            for (int j = 0; j < 8; j++) {
                float4 v = src[j * 8];
                *reinterpret_cast<uint2*>(dstrow + (sub + j * 8) * 8) =
                    make_uint2(packbf(v.x, v.y), packbf(v.z, v.w));
            }
        }
    }
    // --- stage B (W): 8 threads per row, 8 passes of 32 rows ---
    {
        const int sub = tid & 7;
        #pragma unroll
        for (int p = 0; p < 8; p++) {
            const int r = p * 32 + (tid >> 3);
            const float4* src = reinterpret_cast<const float4*>(W + (size_t)r * E_DIM) + sub;
            char* dstrow = smem + BS_OFF + r * (APAD * 2);
            #pragma unroll
            for (int j = 0; j < 8; j++) {
                float4 v = src[j * 8];
                *reinterpret_cast<uint2*>(dstrow + (sub + j * 8) * 8) =
                    make_uint2(packbf(v.x, v.y), packbf(v.z, v.w));
            }
        }
    }
    __syncthreads();

    // --- MMA: warp w computes rows m0..m0+15, all 256 cols, K=256 in 16 steps ---
    const int m0 = wid * 16;
    float c[32][4];
    #pragma unroll
    for (int j = 0; j < 32; j++) { c[j][0] = c[j][1] = c[j][2] = c[j][3] = 0.f; }

    const uint32_t a_addr = sb + AS_OFF + (m0 + (lane & 15)) * (APAD * 2) + (lane >> 4) * 16;
    const uint32_t b_addr = sb + BS_OFF + (lane & 7) * (APAD * 2) + ((lane >> 3) & 1) * 16;

    for (int k = 0; k < 16; k++) {               // k0 = k*16 elems = k*32 bytes
        uint32_t a[4];
        ldsm_x4(a, a_addr + k * 32);
        #pragma unroll
        for (int j = 0; j < 32; j++) {
            uint32_t b[2];
            ldsm_x2(b, b_addr + j * 8 * (APAD * 2) + k * 32);
            mma_bf16(c[j], a, b);
        }
    }

    // --- store C directly to g_xw[t][b][u] ---
    float* outp = g_xw + (size_t)t * (B_DIM * U_DIM);
    const int r0 = m0 + (lane >> 2), c0 = (lane & 3) * 2;
    #pragma unroll
    for (int j = 0; j < 32; j++) {
        const int col = j * 8 + c0;
        *reinterpret_cast<float2*>(outp + r0 * U_DIM + col)       = make_float2(c[j][0], c[j][1]);
        *reinterpret_cast<float2*>(outp + (r0 + 8) * U_DIM + col) = make_float2(c[j][2], c[j][3]);
    }
}

// ---------------- Kernel 2: recurrence + head ----------------
// 128 CTAs (one batch row each), 256 threads (one output unit each).
// U packed transposed in smem: P[kk][u] = uint2 of bf16x2 for k=4kk..4kk+3.
// h double-buffered fp32 in smem.

static constexpr int RNN_P_BYTES = 64 * 256 * 8;               // 131072
static constexpr int RNN_SMEM_BYTES = RNN_P_BYTES + 2048 + 256;

__global__ void __launch_bounds__(256, 1)
rnn_kernel(const float* __restrict__ Um, const float* __restrict__ W1,
           const float* __restrict__ b1, const float* __restrict__ W2,
           const float* __restrict__ b2, float* __restrict__ out) {
    extern __shared__ char smem[];
    uint2* P   = reinterpret_cast<uint2*>(smem);
    float* h   = reinterpret_cast<float*>(smem + RNN_P_BYTES);
    float* hid = h + 512;
    const int tid = threadIdx.x;
    const int b   = blockIdx.x;
    const int u   = tid;

    // Load U row u -> packed transposed layout
    {
        const float4* src = reinterpret_cast<const float4*>(Um + u * U_DIM);
        #pragma unroll 4
        for (int f = 0; f < 64; f++) {
            float4 v = src[f];
            P[f * 256 + u] = make_uint2(packbf(v.x, v.y), packbf(v.z, v.w));
        }
    }
    h[u] = 0.0f;  // buffer 0 = initial state
    __syncthreads();

    const float* xwb = g_xw + (size_t)b * U_DIM + u;
    const uint2* Pu = P + u;

    for (int t = 0; t < T_DIM; t++) {
        float xw = xwb[(size_t)t * (B_DIM * U_DIM)];   // prefetched early, used late
        const float* hp = h + ((t & 1) << 8);
        float a0 = 0.f, a1 = 0.f, a2 = 0.f, a3 = 0.f;
        #pragma unroll 8
        for (int kk = 0; kk < 64; kk++) {
            uint2 w = Pu[kk * 256];
            float4 hv = *reinterpret_cast<const float4*>(hp + (kk << 2));
            a0 += blo(w.x) * hv.x;
            a1 += bhi(w.x) * hv.y;
            a2 += blo(w.y) * hv.z;
            a3 += bhi(w.y) * hv.w;
        }
        float s = ((a0 + a1) + (a2 + a3)) + xw;
        float hn = tanhf(s);
        h[(((t & 1) ^ 1) << 8) + u] = hn;
        __syncthreads();
    }

    // Head: final h in buffer 0 (t=511 wrote buffer 0)
    const float* hf = h;
    if (tid < 32) {
        float a = b1[tid];
        #pragma unroll 8
        for (int k = 0; k < 256; k++) a += hf[k] * W1[k * 32 + tid];
        hid[tid] = fmaxf(a, 0.0f);
    }
    __syncthreads();
    if (tid == 0) {
        float l0 = b2[0], l1 = b2[1];
        #pragma unroll
        for (int j = 0; j < 32; j++) {
            float x = hid[j];
            l0 += x * W2[j * 2 + 0];
            l1 += x * W2[j * 2 + 1];
        }
        float mx = fmaxf(l0, l1);
        float e0 = __expf(l0 - mx), e1 = __expf(l1 - mx);
        float inv = 1.0f / (e0 + e1);
        out[b * 2 + 0] = e0 * inv;
        out[b * 2 + 1] = e1 * inv;
    }
}

// ---------------- launch ----------------
extern "C" void kernel_launch(void* const* d_in, const int* in_sizes, int n_in,
                              void* d_out, int out_size) {
    const int*   sentence = (const int*)  d_in[0];
    const float* emb      = (const float*)d_in[1];
    const float* W        = (const float*)d_in[2];
    const float* Um       = (const float*)d_in[3];
    const float* W1       = (const float*)d_in[4];
    const float* b1       = (const float*)d_in[5];
    const float* W2       = (const float*)d_in[6];
    const float* b2       = (const float*)d_in[7];
    float* out = (float*)d_out;

    cudaFuncSetAttribute(xw_kernel,  cudaFuncAttributeMaxDynamicSharedMemorySize, XW_SMEM);
    cudaFuncSetAttribute(rnn_kernel, cudaFuncAttributeMaxDynamicSharedMemorySize, RNN_SMEM_BYTES);

    xw_kernel<<<T_DIM, 256, XW_SMEM>>>(sentence, emb, W);
    rnn_kernel<<<B_DIM, 256, RNN_SMEM_BYTES>>>(Um, W1, b1, W2, b2, out);
}

// round 3
// speedup vs baseline: 1.2726x; 1.2726x over previous
#include <cuda_runtime.h>
#include <cuda_bf16.h>
#include <cstdint>

#define T_DIM 512
#define B_DIM 128
#define E_DIM 256
#define U_DIM 256

// Scratch for xW[t][b][u]  (64 MB fp32 — fits in 126 MB L2)
__device__ float g_xw[T_DIM * B_DIM * U_DIM];

// ---------------- helpers ----------------
__device__ __forceinline__ uint32_t smem_u32(const void* p) {
    uint32_t a;
    asm("{ .reg .u64 t; cvta.to.shared.u64 t, %1; cvt.u32.u64 %0, t; }" : "=r"(a) : "l"(p));
    return a;
}
__device__ __forceinline__ uint32_t packbf(float a, float b) {
    __nv_bfloat162 t = __floats2bfloat162_rn(a, b);
    return *reinterpret_cast<uint32_t*>(&t);
}
__device__ __forceinline__ float blo(uint32_t v) { return __uint_as_float(v << 16); }
__device__ __forceinline__ float bhi(uint32_t v) { return __uint_as_float(v & 0xffff0000u); }

__device__ __forceinline__ void ldsm_x4(uint32_t* r, uint32_t addr) {
    asm volatile("ldmatrix.sync.aligned.m8n8.x4.shared.b16 {%0,%1,%2,%3}, [%4];"
                 : "=r"(r[0]), "=r"(r[1]), "=r"(r[2]), "=r"(r[3]) : "r"(addr));
}
__device__ __forceinline__ void ldsm_x2(uint32_t* r, uint32_t addr) {
    asm volatile("ldmatrix.sync.aligned.m8n8.x2.shared.b16 {%0,%1}, [%2];"
                 : "=r"(r[0]), "=r"(r[1]) : "r"(addr));
}
__device__ __forceinline__ void mma_bf16(float* c, const uint32_t* a, const uint32_t* b) {
    asm volatile("mma.sync.aligned.m16n8k16.row.col.f32.bf16.bf16.f32 "
                 "{%0,%1,%2,%3}, {%4,%5,%6,%7}, {%8,%9}, {%0,%1,%2,%3};"
                 : "+f"(c[0]), "+f"(c[1]), "+f"(c[2]), "+f"(c[3])
                 : "r"(a[0]), "r"(a[1]), "r"(a[2]), "r"(a[3]), "r"(b[0]), "r"(b[1]));
}

// Packed fp32 pair FMA (Blackwell): acc = a*b + acc, two fp32 lanes per issue.
__device__ __forceinline__ void fma2(unsigned long long& acc, unsigned long long a,
                                     unsigned long long b) {
    asm("fma.rn.f32x2 %0, %1, %2, %0;" : "+l"(acc) : "l"(a), "l"(b));
}
__device__ __forceinline__ unsigned long long packf2(float a, float b) {
    unsigned long long r;
    asm("mov.b64 %0, {%1, %2};" : "=l"(r) : "f"(a), "f"(b));
    return r;
}
__device__ __forceinline__ float2 unpackf2(unsigned long long v) {
    float2 r;
    asm("mov.b64 {%0, %1}, %2;" : "=f"(r.x), "=f"(r.y) : "l"(v));
    return r;
}
__device__ __forceinline__ void lds_v2b64(unsigned long long& a, unsigned long long& b,
                                          uint32_t addr) {
    asm volatile("ld.shared.v2.b64 {%0, %1}, [%2];" : "=l"(a), "=l"(b) : "r"(addr));
}

// ---------------- Kernel 1: xW[t][b][u] = emb[token(b,t)] . W[u] ----------------
// One CTA per timestep t (512 CTAs, 256 threads / 8 warps).

static constexpr int APAD = 264;                     // bf16 elems per smem row
static constexpr int AS_OFF = 0;
static constexpr int BS_OFF = 128 * APAD * 2;        // 67584
static constexpr int XW_SMEM = BS_OFF + 256 * APAD * 2;  // 202752

__global__ void __launch_bounds__(256, 1)
xw_kernel(const int* __restrict__ sentence, const float* __restrict__ emb,
          const float* __restrict__ W) {
    extern __shared__ char smem[];
    const int tid = threadIdx.x, t = blockIdx.x;
    const int wid = tid >> 5, lane = tid & 31;
    const uint32_t sb = smem_u32(smem);

    // stage A (emb rows of this timestep's tokens)
    {
        const int sub = tid & 7;
        #pragma unroll
        for (int p = 0; p < 4; p++) {
            const int r = p * 32 + (tid >> 3);
            const int tok = sentence[r * T_DIM + t];
            const float4* src = reinterpret_cast<const float4*>(emb + (size_t)tok * E_DIM) + sub;
            char* dstrow = smem + AS_OFF + r * (APAD * 2);
            #pragma unroll
            for (int j = 0; j < 8; j++) {
                float4 v = src[j * 8];
                *reinterpret_cast<uint2*>(dstrow + (sub + j * 8) * 8) =
                    make_uint2(packbf(v.x, v.y), packbf(v.z, v.w));
            }
        }
    }
    // stage B (W rows)
    {
        const int sub = tid & 7;
        #pragma unroll
        for (int p = 0; p < 8; p++) {
            const int r = p * 32 + (tid >> 3);
            const float4* src = reinterpret_cast<const float4*>(W + (size_t)r * E_DIM) + sub;
            char* dstrow = smem + BS_OFF + r * (APAD * 2);
            #pragma unroll
            for (int j = 0; j < 8; j++) {
                float4 v = src[j * 8];
                *reinterpret_cast<uint2*>(dstrow + (sub + j * 8) * 8) =
                    make_uint2(packbf(v.x, v.y), packbf(v.z, v.w));
            }
        }
    }
    __syncthreads();

    const int m0 = wid * 16;
    float c[32][4];
    #pragma unroll
    for (int j = 0; j < 32; j++) { c[j][0] = c[j][1] = c[j][2] = c[j][3] = 0.f; }

    const uint32_t a_addr = sb + AS_OFF + (m0 + (lane & 15)) * (APAD * 2) + (lane >> 4) * 16;
    const uint32_t b_addr = sb + BS_OFF + (lane & 7) * (APAD * 2) + ((lane >> 3) & 1) * 16;

    for (int k = 0; k < 16; k++) {
        uint32_t a[4];
        ldsm_x4(a, a_addr + k * 32);
        #pragma unroll
        for (int j = 0; j < 32; j++) {
            uint32_t b[2];
            ldsm_x2(b, b_addr + j * 8 * (APAD * 2) + k * 32);
            mma_bf16(c[j], a, b);
        }
    }

    float* outp = g_xw + (size_t)t * (B_DIM * U_DIM);
    const int r0 = m0 + (lane >> 2), c0 = (lane & 3) * 2;
    #pragma unroll
    for (int j = 0; j < 32; j++) {
        const int col = j * 8 + c0;
        *reinterpret_cast<float2*>(outp + r0 * U_DIM + col)       = make_float2(c[j][0], c[j][1]);
        *reinterpret_cast<float2*>(outp + (r0 + 8) * U_DIM + col) = make_float2(c[j][2], c[j][3]);
    }
}

// ---------------- Kernel 2: recurrence + head ----------------
// 128 CTAs (one batch row each), 256 threads (one output unit each).
// U row u, k in [0,176): 88 f32x2 pairs in REGISTERS (no smem traffic, no unpack).
// U row u, k in [176,256): bf16x2-packed transposed smem (uint4 = 8 k-values).
// h double-buffered fp32 in smem; read as v2.b64 pairs (f32x2 operands) + float4.

static constexpr int KREG = 176;                       // k-range covered by registers
static constexpr int KSM  = U_DIM - KREG;              // 80 in smem
static constexpr int NP4  = KSM / 8;                   // 10 uint4 groups
static constexpr int PS_BYTES = NP4 * 256 * 16;        // 40960
static constexpr int RNN_SMEM_BYTES = PS_BYTES + 2048 + 256;

__global__ void __launch_bounds__(256, 1)
rnn_kernel(const float* __restrict__ Um, const float* __restrict__ W1,
           const float* __restrict__ b1, const float* __restrict__ W2,
           const float* __restrict__ b2, float* __restrict__ out) {
    extern __shared__ char smem[];
    uint4* Ps  = reinterpret_cast<uint4*>(smem);
    float* h   = reinterpret_cast<float*>(smem + PS_BYTES);
    float* hid = h + 512;
    const uint32_t h_addr = smem_u32(h);
    const int tid = threadIdx.x;
    const int b   = blockIdx.x;
    const int u   = tid;

    // --- one-time: U row u -> 88 f32x2 regs (k<176) + smem bf16x2 (k>=176) ---
    unsigned long long ur[KREG / 2];
    {
        const float2* src = reinterpret_cast<const float2*>(Um + (size_t)u * U_DIM);
        #pragma unroll
        for (int i = 0; i < KREG / 2; i++) {
            float2 v = src[i];
            ur[i] = packf2(v.x, v.y);
        }
        const float4* src4 = reinterpret_cast<const float4*>(Um + (size_t)u * U_DIM + KREG);
        #pragma unroll
        for (int j = 0; j < NP4; j++) {
            float4 a = src4[j * 2];
            float4 c = src4[j * 2 + 1];
            Ps[j * 256 + u] = make_uint4(packbf(a.x, a.y), packbf(a.z, a.w),
                                         packbf(c.x, c.y), packbf(c.z, c.w));
        }
    }
    h[u] = 0.0f;  // buffer 0 = initial state
    __syncthreads();

    const float* xwb = g_xw + (size_t)b * U_DIM + u;
    const uint4* Pu = Ps + u;

    for (int t = 0; t < T_DIM; t++) {
        float xw = xwb[(size_t)t * (B_DIM * U_DIM)];   // L2 hit, used late
        const uint32_t hb = h_addr + ((t & 1) << 10);  // byte base of current h buffer

        unsigned long long acc[8];
        #pragma unroll
        for (int i = 0; i < 8; i++) acc[i] = 0ull;

        // register part: k in [0,176)
        #pragma unroll
        for (int j = 0; j < KREG / 4; j++) {           // 44 iters, 4 k each
            unsigned long long h0, h1;
            lds_v2b64(h0, h1, hb + j * 16);
            fma2(acc[(2 * j) & 7],     ur[2 * j],     h0);
            fma2(acc[(2 * j + 1) & 7], ur[2 * j + 1], h1);
        }

        // smem part: k in [176,256)
        const float* hp = h + ((t & 1) << 8) + KREG;
        float s0 = 0.f, s1 = 0.f, s2 = 0.f, s3 = 0.f;
        #pragma unroll
        for (int j = 0; j < NP4; j++) {
            uint4 w = Pu[j * 256];
            float4 ha = *reinterpret_cast<const float4*>(hp + j * 8);
            float4 hc = *reinterpret_cast<const float4*>(hp + j * 8 + 4);
            s0 += blo(w.x) * ha.x;  s1 += bhi(w.x) * ha.y;
            s2 += blo(w.y) * ha.z;  s3 += bhi(w.y) * ha.w;
            s0 += blo(w.z) * hc.x;  s1 += bhi(w.z) * hc.y;
            s2 += blo(w.w) * hc.z;  s3 += bhi(w.w) * hc.w;
        }

        float r = ((s0 + s1) + (s2 + s3)) + xw;
        #pragma unroll
        for (int i = 0; i < 8; i += 2) {
            float2 e0 = unpackf2(acc[i]);
            float2 e1 = unpackf2(acc[i + 1]);
            r += ((e0.x + e0.y) + (e1.x + e1.y));
        }
        float hn;
        asm("tanh.approx.f32 %0, %1;" : "=f"(hn) : "f"(r));
        h[(((t & 1) ^ 1) << 8) + u] = hn;
        __syncthreads();
    }

    // Head: final h in buffer 0 (t=511 wrote buffer 0)
    const float* hf = h;
    if (tid < 32) {
        float a = b1[tid];
        #pragma unroll 8
        for (int k = 0; k < 256; k++) a += hf[k] * W1[k * 32 + tid];
        hid[tid] = fmaxf(a, 0.0f);
    }
    __syncthreads();
    if (tid == 0) {
        float l0 = b2[0], l1 = b2[1];
        #pragma unroll
        for (int j = 0; j < 32; j++) {
            float x = hid[j];
            l0 += x * W2[j * 2 + 0];
            l1 += x * W2[j * 2 + 1];
        }
        float mx = fmaxf(l0, l1);
        float e0 = __expf(l0 - mx), e1 = __expf(l1 - mx);
        float inv = 1.0f / (e0 + e1);
        out[b * 2 + 0] = e0 * inv;
        out[b * 2 + 1] = e1 * inv;
    }
}

// ---------------- launch ----------------
extern "C" void kernel_launch(void* const* d_in, const int* in_sizes, int n_in,
                              void* d_out, int out_size) {
    const int*   sentence = (const int*)  d_in[0];
    const float* emb      = (const float*)d_in[1];
    const float* W        = (const float*)d_in[2];
    const float* Um       = (const float*)d_in[3];
    const float* W1       = (const float*)d_in[4];
    const float* b1       = (const float*)d_in[5];
    const float* W2       = (const float*)d_in[6];
    const float* b2       = (const float*)d_in[7];
    float* out = (float*)d_out;

    cudaFuncSetAttribute(xw_kernel,  cudaFuncAttributeMaxDynamicSharedMemorySize, XW_SMEM);
    cudaFuncSetAttribute(rnn_kernel, cudaFuncAttributeMaxDynamicSharedMemorySize, RNN_SMEM_BYTES);

    xw_kernel<<<T_DIM, 256, XW_SMEM>>>(sentence, emb, W);
    rnn_kernel<<<B_DIM, 256, RNN_SMEM_BYTES>>>(Um, W1, b1, W2, b2, out);
}